// round 1
// baseline (speedup 1.0000x reference)
#include <cuda_runtime.h>

// Problem constants
#define BB 256
#define TT 1024
#define VV 6
#define DD 64
#define UU 64
#define GG 256   // 4*U gate columns

// Precomputed per-vocab tables (V=6): xproj rows and mask bits.
__device__ float g_xprojF[VV][GG];
__device__ float g_xprojB[VV][GG];
__device__ int   g_maskv[VV];

__device__ __forceinline__ float sigmoid_fast(float x) {
    return __fdividef(1.f, 1.f + __expf(-x));
}
__device__ __forceinline__ float tanh_fast(float x) {
    return 2.f * __fdividef(1.f, 1.f + __expf(-2.f * x)) - 1.f;
}

// Precompute: xprojF[v][g] = emb[v] . Wk_f[:,g] + b_f[g]; same for backward;
// mask_v[v] = any(emb[v] != 0).
__global__ void precompute_kernel(const float* __restrict__ emb,
                                  const float* __restrict__ Wk_f,
                                  const float* __restrict__ b_f,
                                  const float* __restrict__ Wk_b,
                                  const float* __restrict__ b_b) {
    int v = blockIdx.x;
    int g = threadIdx.x;
    float sf = 0.f, sb = 0.f;
    #pragma unroll 8
    for (int k = 0; k < DD; k++) {
        float e = emb[v * DD + k];
        sf = fmaf(e, Wk_f[k * GG + g], sf);
        sb = fmaf(e, Wk_b[k * GG + g], sb);
    }
    g_xprojF[v][g] = sf + b_f[g];
    g_xprojB[v][g] = sb + b_b[g];
    if (g == 0) {
        int m = 0;
        for (int k = 0; k < DD; k++) m |= (emb[v * DD + k] != 0.f);
        g_maskv[v] = m;
    }
}

// One CTA per batch element. 256 threads; thread t owns gate column
// col = gi*64 + u with u = t>>2, gi = t&3 (quad = one LSTM unit's 4 gates).
// Wr_f column weights held in registers (64 regs/thread). h double-buffered
// in smem, one __syncthreads per step.
__global__ void __launch_bounds__(256, 2)
lstm_fwd_kernel(const int* __restrict__ tokens,
                const float* __restrict__ Wr_f,
                const float* __restrict__ Wd,
                const float* __restrict__ bd,
                float* __restrict__ out) {
    __shared__ float sh_xF[VV * GG];     // 6 KB: forward xproj table
    __shared__ int   sh_tok[TT];         // 4 KB: this batch's token row
    __shared__ float sh_h[2][UU];        // double-buffered hidden state
    __shared__ int   sh_mask[VV];
    __shared__ float sh_red[2];

    const int b    = blockIdx.x;
    const int t    = threadIdx.x;
    const int u    = t >> 2;
    const int gi   = t & 3;
    const int col  = gi * UU + u;
    const int lane = t & 31;
    const int qb   = lane & ~3;          // quad base lane

    // Load recurrent weight column into registers (one-time, amortized over T).
    float w[UU];
    #pragma unroll
    for (int k = 0; k < UU; k++) w[k] = Wr_f[k * GG + col];

    // Stage tokens + tables into smem.
    for (int i = t; i < TT; i += 256) sh_tok[i] = tokens[b * TT + i];
    for (int i = t; i < VV * GG; i += 256) sh_xF[i] = (&g_xprojF[0][0])[i];
    if (t < VV) sh_mask[t] = g_maskv[t];
    if (t < UU) { sh_h[0][t] = 0.f; sh_h[1][t] = 0.f; }
    __syncthreads();

    float c = 0.f;   // cell state, live only in gi==3 lanes

    for (int s = 0; s < TT; s++) {
        const float* __restrict__ hr = sh_h[s & 1];
        float*       __restrict__ hw = sh_h[(s + 1) & 1];

        int   tok = sh_tok[s];
        float z   = sh_xF[tok * GG + col];

        // z += h . Wr[:, col]  — 4 independent accumulator chains.
        float a0 = 0.f, a1 = 0.f, a2 = 0.f, a3 = 0.f;
        #pragma unroll
        for (int k = 0; k < UU; k += 4) {
            float4 h4 = *reinterpret_cast<const float4*>(&hr[k]);
            a0 = fmaf(h4.x, w[k + 0], a0);
            a1 = fmaf(h4.y, w[k + 1], a1);
            a2 = fmaf(h4.z, w[k + 2], a2);
            a3 = fmaf(h4.w, w[k + 3], a3);
        }
        z += (a0 + a1) + (a2 + a3);

        // Activation: gi==2 is the g-gate (tanh), others sigmoid.
        float a = (gi == 2) ? tanh_fast(z) : sigmoid_fast(z);

        // Gather i,f,g into the o-lane (gi==3) via intra-quad shuffles.
        float vi = __shfl_sync(0xffffffffu, a, qb + 0);
        float vf = __shfl_sync(0xffffffffu, a, qb + 1);
        float vg = __shfl_sync(0xffffffffu, a, qb + 2);

        if (gi == 3) {
            float cn = fmaf(vf, c, vi * vg);
            float hn = a * tanh_fast(cn);
            int   m  = sh_mask[tok];
            float ho = hr[u];
            c        = m ? cn : c;
            hw[u]    = m ? hn : ho;
        }
        __syncthreads();
    }

    // Final forward hidden state is in sh_h[0] (step 1023 wrote buffer (1024&1)=0).
    // Backward direction contributes only its FIRST step (h0=c0=0):
    //   z = xprojB(x[T-1]);  c = i*g;  h_b = o*tanh(c);  masked -> 0 if !m.
    if (t < UU) {
        int   tokL = sh_tok[TT - 1];
        float zi = g_xprojB[tokL][t];
        float zg = g_xprojB[tokL][2 * UU + t];
        float zo = g_xprojB[tokL][3 * UU + t];
        float ii = sigmoid_fast(zi);
        float gg = tanh_fast(zg);
        float oo = sigmoid_fast(zo);
        float hb = oo * tanh_fast(ii * gg);
        if (!sh_mask[tokL]) hb = 0.f;

        float contrib = sh_h[0][t] * Wd[t] + hb * Wd[UU + t];
        #pragma unroll
        for (int off = 16; off > 0; off >>= 1)
            contrib += __shfl_down_sync(0xffffffffu, contrib, off);
        if ((t & 31) == 0) sh_red[t >> 5] = contrib;
    }
    __syncthreads();
    if (t == 0) out[b] = sh_red[0] + sh_red[1] + bd[0];
}

// Input order (metadata): tokens, emb, Wk_f, Wr_f, b_f, Wk_b, Wr_b, b_b, Wd, bd
extern "C" void kernel_launch(void* const* d_in, const int* in_sizes, int n_in,
                              void* d_out, int out_size) {
    const int*   tokens = (const int*)  d_in[0];
    const float* emb    = (const float*)d_in[1];
    const float* Wk_f   = (const float*)d_in[2];
    const float* Wr_f   = (const float*)d_in[3];
    const float* b_f    = (const float*)d_in[4];
    const float* Wk_b   = (const float*)d_in[5];
    // d_in[6] = Wr_b: provably unused (backward recurrence collapses to step 1 from h0=0)
    const float* b_b    = (const float*)d_in[7];
    const float* Wd     = (const float*)d_in[8];
    const float* bd     = (const float*)d_in[9];
    float*       out    = (float*)d_out;

    precompute_kernel<<<VV, GG>>>(emb, Wk_f, b_f, Wk_b, b_b);
    lstm_fwd_kernel<<<BB, 256>>>(tokens, Wr_f, Wd, bd, out);
}